// round 1
// baseline (speedup 1.0000x reference)
#include <cuda_runtime.h>
#include <cuda_bf16.h>
#include <math.h>

#define T_STEPS 24
#define NN 50000
#define EE 1600000
#define F 16
#define H 64
#define LH 128
#define G4 512   // 4*LH
#define SCAN_NB 98  // ceil(50000/512)

// ---------------- scratch (static device allocations; no cudaMalloc) ----------------
__device__ int   d_deg[NN];
__device__ int   d_rowptr[NN + 1];
__device__ int   d_cursor[NN];
__device__ int   d_csr[EE];
__device__ int   d_blocksum[128];
__device__ int   d_blockoff[128];
__device__ float d_dinv[NN];
__device__ float d_y1[NN * F];        // agg1 output
__device__ float d_h1[NN * H];        // layer1 output
__device__ float d_z2[NN * H];        // agg2 output
__device__ float d_h2[NN * H];        // layer2 output (LSTM input)
__device__ float d_gates[NN * G4];    // LSTM preactivations
__device__ float d_hs[NN * LH];       // LSTM h
__device__ float d_cs[NN * LH];       // LSTM c

// ---------------- CSR build ----------------
__global__ void deg_kernel(const int* __restrict__ ei) {
    int e = blockIdx.x * 256 + threadIdx.x;
    if (e < EE) atomicAdd(&d_deg[ei[EE + e]], 1);   // dst = ei[1][e]
}

__global__ void dinv_kernel() {
    int n = blockIdx.x * 256 + threadIdx.x;
    if (n < NN) d_dinv[n] = rsqrtf((float)d_deg[n] + 1.0f);
}

__global__ void scan_block_kernel() {
    __shared__ int s[512];
    int tid = threadIdx.x;
    int i = blockIdx.x * 512 + tid;
    int v = (i < NN) ? d_deg[i] : 0;
    s[tid] = v;
    __syncthreads();
    #pragma unroll
    for (int off = 1; off < 512; off <<= 1) {
        int t = (tid >= off) ? s[tid - off] : 0;
        __syncthreads();
        s[tid] += t;
        __syncthreads();
    }
    if (i < NN) d_rowptr[i + 1] = s[tid];
    if (tid == 511) d_blocksum[blockIdx.x] = s[511];
}

__global__ void scan_top_kernel() {
    if (threadIdx.x == 0) {
        int run = 0;
        for (int b = 0; b < SCAN_NB; b++) { d_blockoff[b] = run; run += d_blocksum[b]; }
    }
}

__global__ void scan_add_kernel() {
    int i = blockIdx.x * 256 + threadIdx.x;
    if (i == 0) { d_rowptr[0] = 0; d_cursor[0] = 0; }
    if (i < NN) {
        int v = d_rowptr[i + 1] + d_blockoff[i >> 9];
        d_rowptr[i + 1] = v;
        if (i + 1 < NN) d_cursor[i + 1] = v;
    }
}

__global__ void csr_fill_kernel(const int* __restrict__ ei) {
    int e = blockIdx.x * 256 + threadIdx.x;
    if (e < EE) {
        int s = ei[e];
        int d = ei[EE + e];
        int idx = atomicAdd(&d_cursor[d], 1);
        d_csr[idx] = s;
    }
}

// ---------------- GCN aggregation (gather, no atomics) ----------------
// y1 = D^-1/2 (A+I) D^-1/2 x_t   (16 cols)
__global__ void agg1_kernel(const float* __restrict__ x) {
    int tid = threadIdx.x;
    int n = blockIdx.x * 16 + (tid >> 4);
    int c = tid & 15;
    if (n >= NN) return;
    float dn = d_dinv[n];
    float acc = x[n * F + c] * dn * dn;
    int e1 = d_rowptr[n + 1];
    for (int e = d_rowptr[n]; e < e1; e++) {
        int s = d_csr[e];
        acc += x[s * F + c] * (d_dinv[s] * dn);
    }
    d_y1[n * F + c] = acc;
}

// z2 = D^-1/2 (A+I) D^-1/2 h1   (64 cols)
__global__ void agg2_kernel() {
    int tid = threadIdx.x;
    int n = blockIdx.x * 4 + (tid >> 6);
    int c = tid & 63;
    if (n >= NN) return;
    float dn = d_dinv[n];
    float acc = d_h1[n * H + c] * dn * dn;
    int e1 = d_rowptr[n + 1];
    for (int e = d_rowptr[n]; e < e1; e++) {
        int s = d_csr[e];
        acc += d_h1[s * H + c] * (d_dinv[s] * dn);
    }
    d_z2[n * H + c] = acc;
}

// ---------------- GCN dense layers ----------------
// h1 = relu(y1 @ W1 + b1), y1:(N,16), W1:(16,64)
__global__ void mm1_kernel(const float* __restrict__ W1, const float* __restrict__ b1) {
    __shared__ float Ws[F * H];
    __shared__ float bs[H];
    int tid = threadIdx.x;
    for (int i = tid; i < F * H; i += 256) Ws[i] = W1[i];
    if (tid < H) bs[tid] = b1[tid];
    __syncthreads();
    int o = blockIdx.x * 256 + tid;
    if (o >= NN * H) return;
    int n = o >> 6, j = o & 63;
    const float* yr = d_y1 + n * F;
    float acc = bs[j];
    #pragma unroll
    for (int k = 0; k < F; k++) acc = fmaf(yr[k], Ws[k * H + j], acc);
    d_h1[o] = fmaxf(acc, 0.0f);
}

// h2 = relu(z2 @ W2 + b2), z2:(N,64), W2:(64,64). 32 nodes/block.
__global__ void mm2_kernel(const float* __restrict__ W2, const float* __restrict__ b2) {
    __shared__ float Ws[H * H];
    __shared__ float bs[H];
    __shared__ float Zs[4][H];
    int tid = threadIdx.x;
    for (int i = tid; i < H * H; i += 256) Ws[i] = W2[i];
    if (tid < H) bs[tid] = b2[tid];
    int j = tid & 63, nl = tid >> 6;
    __syncthreads();
    for (int r = 0; r < 8; r++) {
        int n = blockIdx.x * 32 + r * 4 + nl;
        if (n < NN) Zs[nl][j] = d_z2[n * H + j];
        __syncthreads();
        if (n < NN) {
            float acc = bs[j];
            #pragma unroll
            for (int k = 0; k < H; k++) acc = fmaf(Zs[nl][k], Ws[k * H + j], acc);
            d_h2[n * H + j] = fmaxf(acc, 0.0f);
        }
        __syncthreads();
    }
}

// ---------------- LSTM gates GEMM ----------------
// gates(N,512) = [h2 (N,64) | h_prev (N,128)] @ [W_ih.T ; W_hh.T]   (K = 192)
#define GBM 128
#define GBN 64
#define GBK 16
__global__ void __launch_bounds__(256) gates_gemm(const float* __restrict__ Wih,
                                                  const float* __restrict__ Whh) {
    __shared__ float As[GBM][GBK + 1];
    __shared__ float Bs[GBK][GBN + 1];
    int tid = threadIdx.x;
    int row0 = blockIdx.y * GBM;
    int col0 = blockIdx.x * GBN;
    int tx = tid & 15, ty = tid >> 4;
    float acc[8][4];
    #pragma unroll
    for (int i = 0; i < 8; i++)
        #pragma unroll
        for (int j = 0; j < 4; j++) acc[i][j] = 0.0f;

    for (int k0 = 0; k0 < 192; k0 += GBK) {
        // A tile: 128 rows x 16 cols, float4 loads along K
        #pragma unroll
        for (int i = 0; i < 2; i++) {
            int idx = tid + i * 256;        // 0..511
            int m = idx >> 2, kq = idx & 3;
            int n = row0 + m;
            int gk = k0 + kq * 4;
            float4 v = make_float4(0.f, 0.f, 0.f, 0.f);
            if (n < NN) {
                if (gk < 64) v = *(const float4*)(d_h2 + n * 64 + gk);
                else         v = *(const float4*)(d_hs + n * 128 + (gk - 64));
            }
            As[m][kq * 4 + 0] = v.x;
            As[m][kq * 4 + 1] = v.y;
            As[m][kq * 4 + 2] = v.z;
            As[m][kq * 4 + 3] = v.w;
        }
        // B tile: 64 rows (j = gate col) x 16 cols, from W^T access pattern
        {
            int j = tid >> 2, kq = tid & 3;
            int gj = col0 + j;
            int gk = k0 + kq * 4;
            float4 v;
            if (gk < 64) v = *(const float4*)(Wih + gj * 64 + gk);
            else         v = *(const float4*)(Whh + gj * 128 + (gk - 64));
            Bs[kq * 4 + 0][j] = v.x;
            Bs[kq * 4 + 1][j] = v.y;
            Bs[kq * 4 + 2][j] = v.z;
            Bs[kq * 4 + 3][j] = v.w;
        }
        __syncthreads();
        #pragma unroll
        for (int k = 0; k < GBK; k++) {
            float a[8], b[4];
            #pragma unroll
            for (int i = 0; i < 8; i++) a[i] = As[ty * 8 + i][k];
            #pragma unroll
            for (int j = 0; j < 4; j++) b[j] = Bs[k][tx * 4 + j];
            #pragma unroll
            for (int i = 0; i < 8; i++)
                #pragma unroll
                for (int j = 0; j < 4; j++) acc[i][j] = fmaf(a[i], b[j], acc[i][j]);
        }
        __syncthreads();
    }
    #pragma unroll
    for (int i = 0; i < 8; i++) {
        int n = row0 + ty * 8 + i;
        if (n < NN) {
            float4 v = make_float4(acc[i][0], acc[i][1], acc[i][2], acc[i][3]);
            *(float4*)(d_gates + (size_t)n * G4 + col0 + tx * 4) = v;
        }
    }
}

// ---------------- LSTM pointwise update ----------------
__global__ void lstm_update(const float* __restrict__ bih, const float* __restrict__ bhh) {
    int idx = blockIdx.x * 256 + threadIdx.x;
    if (idx >= NN * LH) return;
    int n = idx >> 7, j = idx & 127;
    const float* g = d_gates + (size_t)n * G4;
    float gi = g[j]           + bih[j]           + bhh[j];
    float gf = g[LH + j]      + bih[LH + j]      + bhh[LH + j];
    float gg = g[2 * LH + j]  + bih[2 * LH + j]  + bhh[2 * LH + j];
    float go = g[3 * LH + j]  + bih[3 * LH + j]  + bhh[3 * LH + j];
    float si = 1.0f / (1.0f + expf(-gi));
    float sf = 1.0f / (1.0f + expf(-gf));
    float so = 1.0f / (1.0f + expf(-go));
    float c = sf * d_cs[idx] + si * tanhf(gg);
    d_cs[idx] = c;
    d_hs[idx] = so * tanhf(c);
}

// ---------------- FC head ----------------
// out[n] = relu(h @ Wf1 + bf1) @ Wf2 + bf2 ;  32 nodes/block, warp per node chunk
__global__ void fc_kernel(const float* __restrict__ Wf1, const float* __restrict__ bf1,
                          const float* __restrict__ Wf2, const float* __restrict__ bf2,
                          float* __restrict__ out) {
    __shared__ float Ws[LH * 32];       // 16 KB
    __shared__ float hsm[32][LH];       // 16 KB
    int tid = threadIdx.x;
    for (int i = tid; i < LH * 32; i += 256) Ws[i] = Wf1[i];
    int n0 = blockIdx.x * 32;
    for (int i = tid; i < 32 * LH; i += 256) {
        int nl = i >> 7, k = i & 127;
        int n = n0 + nl;
        hsm[nl][k] = (n < NN) ? d_hs[n * LH + k] : 0.0f;
    }
    __syncthreads();
    int w = tid >> 5, lane = tid & 31;
    float wf2 = Wf2[lane];
    float bb1 = bf1[lane];
    for (int r = 0; r < 4; r++) {
        int nl = w * 4 + r;
        int n = n0 + nl;
        float acc = bb1;
        #pragma unroll
        for (int k = 0; k < LH; k++) acc = fmaf(hsm[nl][k], Ws[k * 32 + lane], acc);
        acc = fmaxf(acc, 0.0f) * wf2;
        #pragma unroll
        for (int off = 16; off > 0; off >>= 1)
            acc += __shfl_down_sync(0xffffffffu, acc, off);
        if (lane == 0 && n < NN) out[n] = acc + bf2[0];
    }
}

// ---------------- launcher ----------------
extern "C" void kernel_launch(void* const* d_in, const int* in_sizes, int n_in,
                              void* d_out, int out_size) {
    const float* x_seq = (const float*)d_in[0];
    const int*   ei    = (const int*)d_in[1];
    const float* W1    = (const float*)d_in[2];
    const float* b1    = (const float*)d_in[3];
    const float* W2    = (const float*)d_in[4];
    const float* b2    = (const float*)d_in[5];
    const float* Wih   = (const float*)d_in[6];
    const float* Whh   = (const float*)d_in[7];
    const float* bih   = (const float*)d_in[8];
    const float* bhh   = (const float*)d_in[9];
    const float* Wf1   = (const float*)d_in[10];
    const float* bf1   = (const float*)d_in[11];
    const float* Wf2   = (const float*)d_in[12];
    const float* bf2   = (const float*)d_in[13];
    float* out = (float*)d_out;

    void *degp, *hsp, *csp;
    cudaGetSymbolAddress(&degp, d_deg);
    cudaGetSymbolAddress(&hsp, d_hs);
    cudaGetSymbolAddress(&csp, d_cs);
    cudaMemsetAsync(degp, 0, NN * sizeof(int));
    cudaMemsetAsync(hsp, 0, NN * LH * sizeof(float));
    cudaMemsetAsync(csp, 0, NN * LH * sizeof(float));

    deg_kernel<<<(EE + 255) / 256, 256>>>(ei);
    dinv_kernel<<<(NN + 255) / 256, 256>>>();
    scan_block_kernel<<<SCAN_NB, 512>>>();
    scan_top_kernel<<<1, 32>>>();
    scan_add_kernel<<<(NN + 255) / 256, 256>>>();
    csr_fill_kernel<<<(EE + 255) / 256, 256>>>(ei);

    for (int t = 0; t < T_STEPS; t++) {
        agg1_kernel<<<(NN + 15) / 16, 256>>>(x_seq + (size_t)t * NN * F);
        mm1_kernel<<<(NN * H + 255) / 256, 256>>>(W1, b1);
        agg2_kernel<<<(NN + 3) / 4, 256>>>();
        mm2_kernel<<<(NN + 31) / 32, 256>>>(W2, b2);
        gates_gemm<<<dim3(G4 / GBN, (NN + GBM - 1) / GBM), 256>>>(Wih, Whh);
        lstm_update<<<(NN * LH + 255) / 256, 256>>>(bih, bhh);
    }
    fc_kernel<<<(NN + 31) / 32, 256>>>(Wf1, bf1, Wf2, bf2, out);
}

// round 3
// speedup vs baseline: 1.2803x; 1.2803x over previous
#include <cuda_runtime.h>
#include <cuda_bf16.h>
#include <math.h>
#include <stdint.h>

#define T_STEPS 24
#define NN 50000
#define EE 1600000
#define F 16
#define H 64
#define LH 128
#define G4 512
#define SCAN_NB 98

#define KPAD 200                         // padded K stride (elements) for smem tiles
#define APLANE (128 * KPAD * 2)          // 51200 B per plane
#define A_OFF 2048
#define B_OFF (A_OFF + 2 * APLANE)       // 104448
#define GATES_SMEM (B_OFF + 2 * APLANE)  // 206848

// ---------------- helpers ----------------
__device__ __forceinline__ uint32_t smem_u32(const void* p) {
    uint32_t a;
    asm("{ .reg .u64 t; cvta.to.shared.u64 t, %1; cvt.u32.u64 %0, t; }" : "=r"(a) : "l"(p));
    return a;
}
__device__ __forceinline__ void ldsm4(uint32_t* r, uint32_t addr) {
    asm volatile("ldmatrix.sync.aligned.m8n8.x4.shared.b16 {%0,%1,%2,%3}, [%4];"
                 : "=r"(r[0]), "=r"(r[1]), "=r"(r[2]), "=r"(r[3]) : "r"(addr));
}
__device__ __forceinline__ void mma16816(float* c, const uint32_t* a, const uint32_t* b) {
    asm volatile(
        "mma.sync.aligned.m16n8k16.row.col.f32.bf16.bf16.f32 "
        "{%0,%1,%2,%3}, {%4,%5,%6,%7}, {%8,%9}, {%0,%1,%2,%3};"
        : "+f"(c[0]), "+f"(c[1]), "+f"(c[2]), "+f"(c[3])
        : "r"(a[0]), "r"(a[1]), "r"(a[2]), "r"(a[3]), "r"(b[0]), "r"(b[1]));
}

// ---------------- scratch ----------------
__device__ int   d_deg[NN];
__device__ int   d_rowptr[NN + 1];
__device__ int   d_cursor[NN];
__device__ int   d_csr[EE];
__device__ int   d_blocksum[128];
__device__ int   d_blockoff[128];
__device__ float d_dinv[NN];
__device__ float d_y1[NN * F];
__device__ float d_h1[NN * H];
__device__ float d_z2[NN * H];
__device__ float d_h2[NN * H];          // LSTM input per step
__device__ float d_hs0[NN * LH];        // LSTM h double buffer
__device__ float d_hs1[NN * LH];
__device__ float d_cs[NN * LH];         // LSTM c (node-major)
__device__ uint4 d_Bp[2 * 512 * 24];    // bf16 hi/lo weights, reordered cols, [p][512][192]

// ---------------- CSR build ----------------
__global__ void deg_kernel(const int* __restrict__ ei) {
    int e = blockIdx.x * 256 + threadIdx.x;
    if (e < EE) atomicAdd(&d_deg[ei[EE + e]], 1);
}
__global__ void dinv_kernel() {
    int n = blockIdx.x * 256 + threadIdx.x;
    if (n < NN) d_dinv[n] = rsqrtf((float)d_deg[n] + 1.0f);
}
__global__ void scan_block_kernel() {
    __shared__ int s[512];
    int tid = threadIdx.x;
    int i = blockIdx.x * 512 + tid;
    int v = (i < NN) ? d_deg[i] : 0;
    s[tid] = v;
    __syncthreads();
    #pragma unroll
    for (int off = 1; off < 512; off <<= 1) {
        int t = (tid >= off) ? s[tid - off] : 0;
        __syncthreads();
        s[tid] += t;
        __syncthreads();
    }
    if (i < NN) d_rowptr[i + 1] = s[tid];
    if (tid == 511) d_blocksum[blockIdx.x] = s[511];
}
__global__ void scan_top_kernel() {
    if (threadIdx.x == 0) {
        int run = 0;
        for (int b = 0; b < SCAN_NB; b++) { d_blockoff[b] = run; run += d_blocksum[b]; }
    }
}
__global__ void scan_add_kernel() {
    int i = blockIdx.x * 256 + threadIdx.x;
    if (i == 0) { d_rowptr[0] = 0; d_cursor[0] = 0; }
    if (i < NN) {
        int v = d_rowptr[i + 1] + d_blockoff[i >> 9];
        d_rowptr[i + 1] = v;
        if (i + 1 < NN) d_cursor[i + 1] = v;
    }
}
__global__ void csr_fill_kernel(const int* __restrict__ ei) {
    int e = blockIdx.x * 256 + threadIdx.x;
    if (e < EE) {
        int s = ei[e];
        int d = ei[EE + e];
        int idx = atomicAdd(&d_cursor[d], 1);
        d_csr[idx] = s;
    }
}

// ---------------- GCN aggregation ----------------
__global__ void agg1_kernel(const float* __restrict__ x) {
    int tid = threadIdx.x;
    int n = blockIdx.x * 16 + (tid >> 4);
    int c = tid & 15;
    if (n >= NN) return;
    float dn = d_dinv[n];
    float acc = x[n * F + c] * dn * dn;
    int e1 = d_rowptr[n + 1];
    for (int e = d_rowptr[n]; e < e1; e++) {
        int s = d_csr[e];
        acc += x[s * F + c] * (d_dinv[s] * dn);
    }
    d_y1[n * F + c] = acc;
}
__global__ void agg2_kernel() {
    int tid = threadIdx.x;
    int n = blockIdx.x * 4 + (tid >> 6);
    int c = tid & 63;
    if (n >= NN) return;
    float dn = d_dinv[n];
    float acc = d_h1[n * H + c] * dn * dn;
    int e1 = d_rowptr[n + 1];
    for (int e = d_rowptr[n]; e < e1; e++) {
        int s = d_csr[e];
        acc += d_h1[s * H + c] * (d_dinv[s] * dn);
    }
    d_z2[n * H + c] = acc;
}

// ---------------- GCN dense layers ----------------
__global__ void mm1_kernel(const float* __restrict__ W1, const float* __restrict__ b1) {
    __shared__ float Ws[F * H];
    __shared__ float bs[H];
    int tid = threadIdx.x;
    for (int i = tid; i < F * H; i += 256) Ws[i] = W1[i];
    if (tid < H) bs[tid] = b1[tid];
    __syncthreads();
    int o = blockIdx.x * 256 + tid;
    if (o >= NN * H) return;
    int n = o >> 6, j = o & 63;
    const float* yr = d_y1 + n * F;
    float acc = bs[j];
    #pragma unroll
    for (int k = 0; k < F; k++) acc = fmaf(yr[k], Ws[k * H + j], acc);
    d_h1[o] = fmaxf(acc, 0.0f);
}
__global__ void mm2_kernel(const float* __restrict__ W2, const float* __restrict__ b2) {
    __shared__ float Ws[H * H];
    __shared__ float bs[H];
    __shared__ float Zs[4][H];
    int tid = threadIdx.x;
    for (int i = tid; i < H * H; i += 256) Ws[i] = W2[i];
    if (tid < H) bs[tid] = b2[tid];
    int j = tid & 63, nl = tid >> 6;
    __syncthreads();
    for (int r = 0; r < 8; r++) {
        int n = blockIdx.x * 32 + r * 4 + nl;
        if (n < NN) Zs[nl][j] = d_z2[n * H + j];
        __syncthreads();
        if (n < NN) {
            float acc = bs[j];
            #pragma unroll
            for (int k = 0; k < H; k++) acc = fmaf(Zs[nl][k], Ws[k * H + j], acc);
            d_h2[n * H + j] = fmaxf(acc, 0.0f);
        }
        __syncthreads();
    }
}

// ---------------- B precompute: hi/lo bf16 split with reordered gate columns ----------------
// Reordered column cg in [0,512): nb=cg>>7, c=cg&127, wn=(c>>6), g=(c>>4)&3, jh=(c>>3)&1, s=c&7
// j_global = nb*32 + wn*16 + jh*8 + s ; original gate col G = g*128 + j_global
// W row G: k<64 -> Wih[G][k] ; else Whh[G][k-64]
__global__ void bprep_kernel(const float* __restrict__ Wih, const float* __restrict__ Whh) {
    int id = blockIdx.x * 256 + threadIdx.x;
    if (id >= 2 * 512 * 24) return;
    int p = id / (512 * 24);
    int rem = id - p * (512 * 24);
    int cg = rem / 24, u = rem % 24;
    int nb = cg >> 7, c = cg & 127;
    int wn = c >> 6, g = (c >> 4) & 3, jh = (c >> 3) & 1, s = c & 7;
    int jg = nb * 32 + wn * 16 + jh * 8 + s;
    int G = g * 128 + jg;
    union { __nv_bfloat16 h[8]; uint4 q; } up;
    #pragma unroll
    for (int e = 0; e < 8; e++) {
        int k = u * 8 + e;
        float v = (k < 64) ? Wih[G * 64 + k] : Whh[G * 128 + (k - 64)];
        __nv_bfloat16 hi = __float2bfloat16_rn(v);
        up.h[e] = p ? __float2bfloat16_rn(v - __bfloat162float(hi)) : hi;
    }
    d_Bp[(size_t)(p * 512 + cg) * 24 + u] = up.q;
}

// ---------------- fused gates GEMM (mma.sync bf16) + LSTM pointwise ----------------
// gates(tile 128 nodes, 128 reordered cols) = A'(128x576) @ B'^T, fp32 accum in regs.
// 3 passes: Ah@Bh, Ah@Bl, Al@Bh. Epilogue: per-thread i,f,g,o -> c,h update.
__global__ void __launch_bounds__(256, 1) gates_mma(const float* __restrict__ bih,
                                                    const float* __restrict__ bhh,
                                                    const float* __restrict__ hprev,
                                                    float* __restrict__ hnext) {
    extern __shared__ char smem[];
    float* bs = (float*)smem;
    int tid = threadIdx.x, lane = tid & 31, wid = tid >> 5;
    int nb = blockIdx.x;              // column block 0..3
    int tile0 = blockIdx.y * 128;     // node base

    for (int j = tid; j < 512; j += 256) bs[j] = bih[j] + bhh[j];

    // stage B hi+lo for this col block: [p][128 local cols][192] -> padded smem
    for (int i = tid; i < 2 * 128 * 24; i += 256) {
        int p = i / (128 * 24);
        int rem = i - p * (128 * 24);
        int col = rem / 24, u = rem % 24;
        uint4 v = d_Bp[(size_t)(p * 512 + nb * 128 + col) * 24 + u];
        *(uint4*)(smem + B_OFF + p * APLANE + col * (KPAD * 2) + u * 16) = v;
    }
    // stage A hi+lo: rows = nodes, k = [h2(64) | hprev(128)]
    for (int i = tid; i < 128 * 24; i += 256) {
        int row = i / 24, u = i % 24;
        int n = tile0 + row;
        int kb = u * 8;
        float v[8];
        if (n < NN) {
            const float* s = (kb < 64) ? (d_h2 + (size_t)n * 64 + kb)
                                       : (hprev + (size_t)n * 128 + (kb - 64));
            float4 p0 = *(const float4*)s;
            float4 p1 = *(const float4*)(s + 4);
            v[0] = p0.x; v[1] = p0.y; v[2] = p0.z; v[3] = p0.w;
            v[4] = p1.x; v[5] = p1.y; v[6] = p1.z; v[7] = p1.w;
        } else {
            #pragma unroll
            for (int e = 0; e < 8; e++) v[e] = 0.0f;
        }
        union { __nv_bfloat16 h[8]; uint4 q; } hi, lo;
        #pragma unroll
        for (int e = 0; e < 8; e++) {
            hi.h[e] = __float2bfloat16_rn(v[e]);
            lo.h[e] = __float2bfloat16_rn(v[e] - __bfloat162float(hi.h[e]));
        }
        *(uint4*)(smem + A_OFF + row * (KPAD * 2) + u * 16) = hi.q;
        *(uint4*)(smem + A_OFF + APLANE + row * (KPAD * 2) + u * 16) = lo.q;
    }
    __syncthreads();

    int wm = wid & 3;                 // row quarter (32 rows)
    int wn = wid >> 2;                // col half (64 cols)
    float acc[2][8][4];
    #pragma unroll
    for (int mi = 0; mi < 2; mi++)
        #pragma unroll
        for (int nt = 0; nt < 8; nt++)
            #pragma unroll
            for (int r = 0; r < 4; r++) acc[mi][nt][r] = 0.0f;

    uint32_t sb = smem_u32(smem);
    int q = lane >> 3, r8 = lane & 7;
    // A ldmatrix lane address components
    uint32_t aRowOff = (uint32_t)((wm * 32 + (q & 1) * 8 + r8) * (KPAD * 2) + ((q >> 1) * 8) * 2);
    // B ldmatrix: per pair pr, matrix q -> nt = 2*pr + (q>>1), khalf = q&1
    uint32_t bRowBase = (uint32_t)((wn * 64 + (q >> 1) * 8 + r8) * (KPAD * 2) + (q & 1) * 16);

    #pragma unroll 1
    for (int pass = 0; pass < 3; pass++) {
        uint32_t aBase = sb + A_OFF + (pass == 2 ? APLANE : 0) + aRowOff;
        uint32_t bBase = sb + B_OFF + (pass == 1 ? APLANE : 0) + bRowBase;
        #pragma unroll 1
        for (int ks = 0; ks < 12; ks++) {
            uint32_t a[2][4];
            #pragma unroll
            for (int mi = 0; mi < 2; mi++)
                ldsm4(a[mi], aBase + mi * (16 * KPAD * 2) + ks * 32);
            uint32_t b[8][2];
            #pragma unroll
            for (int pr = 0; pr < 4; pr++) {
                uint32_t t4[4];
                ldsm4(t4, bBase + pr * (16 * KPAD * 2) + ks * 32);
                b[2 * pr][0] = t4[0]; b[2 * pr][1] = t4[1];
                b[2 * pr + 1][0] = t4[2]; b[2 * pr + 1][1] = t4[3];
            }
            #pragma unroll
            for (int mi = 0; mi < 2; mi++)
                #pragma unroll
                for (int nt = 0; nt < 8; nt++)
                    mma16816(acc[mi][nt], a[mi], b[nt]);
        }
    }

    // ---- fused LSTM epilogue (all gates in registers) ----
    // thread lane: gq = lane>>2 (row), t = lane&3 (col pair)
    // accum [mi][nt][h*2+p]: row = wm*32+mi*16+h*8+gq ; local col = wn*64+nt*8+2t+p
    // nt = g*2 + jh ; j_global = nb*32 + wn*16 + jh*8 + 2t + p
    {
        int gq = lane >> 2, t = lane & 3;
        #pragma unroll
        for (int mi = 0; mi < 2; mi++) {
            #pragma unroll
            for (int h = 0; h < 2; h++) {
                int n = tile0 + wm * 32 + mi * 16 + h * 8 + gq;
                bool valid = (n < NN);
                #pragma unroll
                for (int jh = 0; jh < 2; jh++) {
                    #pragma unroll
                    for (int p = 0; p < 2; p++) {
                        int jg = nb * 32 + wn * 16 + jh * 8 + 2 * t + p;
                        int ci = h * 2 + p;
                        float gi = acc[mi][0 + jh][ci] + bs[jg];
                        float gf = acc[mi][2 + jh][ci] + bs[128 + jg];
                        float gG = acc[mi][4 + jh][ci] + bs[256 + jg];
                        float go = acc[mi][6 + jh][ci] + bs[384 + jg];
                        float cp = valid ? d_cs[(size_t)n * LH + jg] : 0.0f;
                        float si = 1.0f / (1.0f + __expf(-gi));
                        float sf = 1.0f / (1.0f + __expf(-gf));
                        float so = 1.0f / (1.0f + __expf(-go));
                        float cn = sf * cp + si * tanhf(gG);
                        if (valid) {
                            d_cs[(size_t)n * LH + jg] = cn;
                            hnext[(size_t)n * LH + jg] = so * tanhf(cn);
                        }
                    }
                }
            }
        }
    }
}

// ---------------- FC head ----------------
__global__ void fc_kernel(const float* __restrict__ hfin,
                          const float* __restrict__ Wf1, const float* __restrict__ bf1,
                          const float* __restrict__ Wf2, const float* __restrict__ bf2,
                          float* __restrict__ out) {
    __shared__ float Ws[LH * 32];
    __shared__ float hsm[32][LH];
    int tid = threadIdx.x;
    for (int i = tid; i < LH * 32; i += 256) Ws[i] = Wf1[i];
    int n0 = blockIdx.x * 32;
    for (int i = tid; i < 32 * LH; i += 256) {
        int nl = i >> 7, k = i & 127;
        int n = n0 + nl;
        hsm[nl][k] = (n < NN) ? hfin[n * LH + k] : 0.0f;
    }
    __syncthreads();
    int w = tid >> 5, lane = tid & 31;
    float wf2 = Wf2[lane];
    float bb1 = bf1[lane];
    for (int r = 0; r < 4; r++) {
        int nl = w * 4 + r;
        int n = n0 + nl;
        float acc = bb1;
        #pragma unroll
        for (int k = 0; k < LH; k++) acc = fmaf(hsm[nl][k], Ws[k * 32 + lane], acc);
        acc = fmaxf(acc, 0.0f) * wf2;
        #pragma unroll
        for (int off = 16; off > 0; off >>= 1)
            acc += __shfl_down_sync(0xffffffffu, acc, off);
        if (lane == 0 && n < NN) out[n] = acc + bf2[0];
    }
}

// ---------------- launcher ----------------
extern "C" void kernel_launch(void* const* d_in, const int* in_sizes, int n_in,
                              void* d_out, int out_size) {
    const float* x_seq = (const float*)d_in[0];
    const int*   ei    = (const int*)d_in[1];
    const float* W1    = (const float*)d_in[2];
    const float* b1    = (const float*)d_in[3];
    const float* W2    = (const float*)d_in[4];
    const float* b2    = (const float*)d_in[5];
    const float* Wih   = (const float*)d_in[6];
    const float* Whh   = (const float*)d_in[7];
    const float* bih   = (const float*)d_in[8];
    const float* bhh   = (const float*)d_in[9];
    const float* Wf1   = (const float*)d_in[10];
    const float* bf1   = (const float*)d_in[11];
    const float* Wf2   = (const float*)d_in[12];
    const float* bf2   = (const float*)d_in[13];
    float* out = (float*)d_out;

    cudaFuncSetAttribute(gates_mma, cudaFuncAttributeMaxDynamicSharedMemorySize, GATES_SMEM);

    void *degp, *hs0p, *csp;
    cudaGetSymbolAddress(&degp, d_deg);
    cudaGetSymbolAddress(&hs0p, d_hs0);
    cudaGetSymbolAddress(&csp, d_cs);
    cudaMemsetAsync(degp, 0, NN * sizeof(int));
    cudaMemsetAsync(hs0p, 0, NN * LH * sizeof(float));
    cudaMemsetAsync(csp, 0, NN * LH * sizeof(float));

    float *hbuf0, *hbuf1;
    cudaGetSymbolAddress((void**)&hbuf0, d_hs0);
    cudaGetSymbolAddress((void**)&hbuf1, d_hs1);

    deg_kernel<<<(EE + 255) / 256, 256>>>(ei);
    dinv_kernel<<<(NN + 255) / 256, 256>>>();
    scan_block_kernel<<<SCAN_NB, 512>>>();
    scan_top_kernel<<<1, 32>>>();
    scan_add_kernel<<<(NN + 255) / 256, 256>>>();
    csr_fill_kernel<<<(EE + 255) / 256, 256>>>(ei);
    bprep_kernel<<<(2 * 512 * 24 + 255) / 256, 256>>>(Wih, Whh);

    dim3 ggrid(4, (NN + 127) / 128);
    for (int t = 0; t < T_STEPS; t++) {
        agg1_kernel<<<(NN + 15) / 16, 256>>>(x_seq + (size_t)t * NN * F);
        mm1_kernel<<<(NN * H + 255) / 256, 256>>>(W1, b1);
        agg2_kernel<<<(NN + 3) / 4, 256>>>();
        mm2_kernel<<<(NN + 31) / 32, 256>>>(W2, b2);
        const float* hp = (t & 1) ? hbuf1 : hbuf0;
        float*       hn = (t & 1) ? hbuf0 : hbuf1;
        gates_mma<<<ggrid, 256, GATES_SMEM>>>(bih, bhh, hp, hn);
    }
    // t=23 (odd) writes hbuf0
    fc_kernel<<<(NN + 31) / 32, 256>>>(hbuf0, Wf1, bf1, Wf2, bf2, out);
}

// round 4
// speedup vs baseline: 1.3870x; 1.0834x over previous
#include <cuda_runtime.h>
#include <cuda_bf16.h>
#include <cuda_fp16.h>
#include <math.h>
#include <stdint.h>

#define T_STEPS 24
#define NN 50000
#define NPAD 50048
#define EE 1600000
#define F 16
#define H 64
#define LH 128
#define SCAN_NB 98

#define KPAD 200                         // padded K stride (halfs) for gates smem tiles
#define APLANE (128 * KPAD * 2)          // 51200 B per plane
#define A_OFF 2048
#define B_OFF (A_OFF + 2 * APLANE)       // 104448
#define GATES_SMEM (B_OFF + 2 * APLANE)  // 206848

// ---------------- helpers ----------------
__device__ __forceinline__ uint32_t smem_u32(const void* p) {
    uint32_t a;
    asm("{ .reg .u64 t; cvta.to.shared.u64 t, %1; cvt.u32.u64 %0, t; }" : "=r"(a) : "l"(p));
    return a;
}
__device__ __forceinline__ void ldsm4(uint32_t* r, uint32_t addr) {
    asm volatile("ldmatrix.sync.aligned.m8n8.x4.shared.b16 {%0,%1,%2,%3}, [%4];"
                 : "=r"(r[0]), "=r"(r[1]), "=r"(r[2]), "=r"(r[3]) : "r"(addr));
}
__device__ __forceinline__ void mma16816(float* c, const uint32_t* a, const uint32_t* b) {
    asm volatile(
        "mma.sync.aligned.m16n8k16.row.col.f32.bf16.bf16.f32 "
        "{%0,%1,%2,%3}, {%4,%5,%6,%7}, {%8,%9}, {%0,%1,%2,%3};"
        : "+f"(c[0]), "+f"(c[1]), "+f"(c[2]), "+f"(c[3])
        : "r"(a[0]), "r"(a[1]), "r"(a[2]), "r"(a[3]), "r"(b[0]), "r"(b[1]));
}

// ---------------- scratch ----------------
__device__ int   d_deg[NN];
__device__ int   d_rowptr[NN + 1];
__device__ int   d_cursor[NN];
__device__ int   d_csr[EE];
__device__ int   d_blocksum[128];
__device__ int   d_blockoff[128];
__device__ float d_dinv[NN];
__device__ __half d_xh[19200000];                 // [n][t*16+c]  (50000*384)
__device__ __half d_h1[76800000];                 // [t][n][64]   (24*50000*64)
__device__ __nv_bfloat16 d_h2h[76873728];         // [t][NPAD][64] hi
__device__ __nv_bfloat16 d_h2l[76873728];         // lo
__device__ __nv_bfloat16 d_hh0[6406144];          // [NPAD][128]
__device__ __nv_bfloat16 d_hl0[6406144];
__device__ __nv_bfloat16 d_hh1[6406144];
__device__ __nv_bfloat16 d_hl1[6406144];
__device__ float d_cs2[6406144];                  // [nb][NPAD][32]
__device__ uint4 d_Bp[2 * 512 * 24];              // bf16 hi/lo weights, reordered cols

// ---------------- CSR build ----------------
__global__ void deg_kernel(const int* __restrict__ ei) {
    int e = blockIdx.x * 256 + threadIdx.x;
    if (e < EE) atomicAdd(&d_deg[ei[EE + e]], 1);
}
__global__ void dinv_kernel() {
    int n = blockIdx.x * 256 + threadIdx.x;
    if (n < NN) d_dinv[n] = rsqrtf((float)d_deg[n] + 1.0f);
}
__global__ void scan_block_kernel() {
    __shared__ int s[512];
    int tid = threadIdx.x;
    int i = blockIdx.x * 512 + tid;
    int v = (i < NN) ? d_deg[i] : 0;
    s[tid] = v;
    __syncthreads();
    #pragma unroll
    for (int off = 1; off < 512; off <<= 1) {
        int t = (tid >= off) ? s[tid - off] : 0;
        __syncthreads();
        s[tid] += t;
        __syncthreads();
    }
    if (i < NN) d_rowptr[i + 1] = s[tid];
    if (tid == 511) d_blocksum[blockIdx.x] = s[511];
}
__global__ void scan_top_kernel() {
    if (threadIdx.x == 0) {
        int run = 0;
        for (int b = 0; b < SCAN_NB; b++) { d_blockoff[b] = run; run += d_blocksum[b]; }
    }
}
__global__ void scan_add_kernel() {
    int i = blockIdx.x * 256 + threadIdx.x;
    if (i == 0) { d_rowptr[0] = 0; d_cursor[0] = 0; }
    if (i < NN) {
        int v = d_rowptr[i + 1] + d_blockoff[i >> 9];
        d_rowptr[i + 1] = v;
        if (i + 1 < NN) d_cursor[i + 1] = v;
    }
}
__global__ void csr_fill_kernel(const int* __restrict__ ei) {
    int e = blockIdx.x * 256 + threadIdx.x;
    if (e < EE) {
        int s = ei[e];
        int d = ei[EE + e];
        int idx = atomicAdd(&d_cursor[d], 1);
        d_csr[idx] = s;
    }
}

// ---------------- x -> fp16 repack: xh[n][t*16+c] ----------------
__global__ void xprep_kernel(const float* __restrict__ x_seq) {
    int id = blockIdx.x * 256 + threadIdx.x;
    if (id >= NN * 96) return;
    int n = id / 96, r = id % 96;          // r = t*4 + c4
    int t = r >> 2, c4 = r & 3;
    float4 v = *(const float4*)(x_seq + ((size_t)t * NN + n) * F + c4 * 4);
    __half h[4] = {__float2half_rn(v.x), __float2half_rn(v.y),
                   __float2half_rn(v.z), __float2half_rn(v.w)};
    *(uint2*)(d_xh + (size_t)n * 384 + r * 4) = *(uint2*)h;
}

// ---------------- fused agg1 + mm1, batched over 8-t chunks ----------------
// warp = node; chunk q covers t = q*8..q*8+7; lane holds 4 cols (t=lane>>2, c=(lane&3)*4..)
__global__ void __launch_bounds__(256) agg1mm1_kernel(const float* __restrict__ W1,
                                                      const float* __restrict__ b1) {
    __shared__ float W1s[F * H];
    __shared__ float b1s[H];
    __shared__ float ys[8][128];
    int tid = threadIdx.x, w = tid >> 5, lane = tid & 31;
    for (int i = tid; i < F * H; i += 256) W1s[i] = W1[i];
    if (tid < H) b1s[tid] = b1[tid];
    int n = blockIdx.x * 8 + w;
    int q = blockIdx.y;
    float dn = d_dinv[n];
    const uint2* xr = (const uint2*)d_xh;
    size_t selfIdx = (size_t)n * 96 + q * 32 + lane;
    uint2 u = xr[selfIdx];
    float2 p0 = __half22float2(*(__half2*)&u.x);
    float2 p1 = __half22float2(*(__half2*)&u.y);
    float sn = dn * dn;
    float a0 = p0.x * sn, a1 = p0.y * sn, a2 = p1.x * sn, a3 = p1.y * sn;
    int e0 = d_rowptr[n], e1 = d_rowptr[n + 1];
    #pragma unroll 4
    for (int e = e0; e < e1; e++) {
        int s = d_csr[e];
        float wgt = d_dinv[s] * dn;
        uint2 v = xr[(size_t)s * 96 + q * 32 + lane];
        float2 q0 = __half22float2(*(__half2*)&v.x);
        float2 q1 = __half22float2(*(__half2*)&v.y);
        a0 = fmaf(q0.x, wgt, a0); a1 = fmaf(q0.y, wgt, a1);
        a2 = fmaf(q1.x, wgt, a2); a3 = fmaf(q1.y, wgt, a3);
    }
    ys[w][lane * 4 + 0] = a0; ys[w][lane * 4 + 1] = a1;
    ys[w][lane * 4 + 2] = a2; ys[w][lane * 4 + 3] = a3;
    __syncthreads();
    // mm1: thread -> (node n2, t2, 16 j's)
    int n2 = tid >> 5, t2 = lane >> 2, jq = lane & 3;
    float yv[16];
    #pragma unroll
    for (int k = 0; k < 16; k++) yv[k] = ys[n2][t2 * 16 + k];
    float o[16];
    #pragma unroll
    for (int jj = 0; jj < 16; jj++) o[jj] = b1s[jq * 16 + jj];
    #pragma unroll
    for (int k = 0; k < 16; k++)
        #pragma unroll
        for (int jj = 0; jj < 16; jj++)
            o[jj] = fmaf(yv[k], W1s[k * 64 + jq * 16 + jj], o[jj]);
    __half hp[16];
    #pragma unroll
    for (int jj = 0; jj < 16; jj++) hp[jj] = __float2half_rn(fmaxf(o[jj], 0.0f));
    int tg = q * 8 + t2;
    int ng = blockIdx.x * 8 + n2;
    __half* dst = d_h1 + ((size_t)tg * NN + ng) * 64 + jq * 16;
    *(uint4*)dst = *(uint4*)hp;
    *(uint4*)(dst + 8) = *(uint4*)(hp + 8);
}

// ---------------- fused agg2 + mm2, batched over 4-t chunks ----------------
// warp = node; lane holds 2 cols per t (c = lane*2, lane*2+1), 4 t's
__global__ void __launch_bounds__(256) agg2mm2_kernel(const float* __restrict__ W2,
                                                      const float* __restrict__ b2) {
    __shared__ float W2s[H * H];
    __shared__ float b2s[H];
    __shared__ float zs[8][4][64];
    int tid = threadIdx.x, w = tid >> 5, lane = tid & 31;
    for (int i = tid; i < H * H; i += 256) W2s[i] = W2[i];
    if (tid < H) b2s[tid] = b2[tid];
    int n = blockIdx.x * 8 + w;
    int q = blockIdx.y;
    float dn = d_dinv[n];
    const uint* h1u = (const uint*)d_h1;
    float acc[4][2];
    float sn = dn * dn;
    #pragma unroll
    for (int tt = 0; tt < 4; tt++) {
        uint u = h1u[((size_t)(q * 4 + tt) * NN + n) * 32 + lane];
        float2 p = __half22float2(*(__half2*)&u);
        acc[tt][0] = p.x * sn; acc[tt][1] = p.y * sn;
    }
    int e0 = d_rowptr[n], e1 = d_rowptr[n + 1];
    #pragma unroll 2
    for (int e = e0; e < e1; e++) {
        int s = d_csr[e];
        float wgt = d_dinv[s] * dn;
        #pragma unroll
        for (int tt = 0; tt < 4; tt++) {
            uint u = h1u[((size_t)(q * 4 + tt) * NN + s) * 32 + lane];
            float2 p = __half22float2(*(__half2*)&u);
            acc[tt][0] = fmaf(p.x, wgt, acc[tt][0]);
            acc[tt][1] = fmaf(p.y, wgt, acc[tt][1]);
        }
    }
    #pragma unroll
    for (int tt = 0; tt < 4; tt++) {
        zs[w][tt][lane * 2] = acc[tt][0];
        zs[w][tt][lane * 2 + 1] = acc[tt][1];
    }
    __syncthreads();
    // mm2: thread -> (n2, t2, 8 j's)
    int n2 = tid >> 5, t2 = (lane >> 3) & 3, j0 = (lane & 7) * 8;
    float o[8];
    #pragma unroll
    for (int jj = 0; jj < 8; jj++) o[jj] = b2s[j0 + jj];
    #pragma unroll 8
    for (int k = 0; k < 64; k++) {
        float zv = zs[n2][t2][k];
        float4 w0 = *(float4*)(W2s + k * 64 + j0);
        float4 w1 = *(float4*)(W2s + k * 64 + j0 + 4);
        o[0] = fmaf(zv, w0.x, o[0]); o[1] = fmaf(zv, w0.y, o[1]);
        o[2] = fmaf(zv, w0.z, o[2]); o[3] = fmaf(zv, w0.w, o[3]);
        o[4] = fmaf(zv, w1.x, o[4]); o[5] = fmaf(zv, w1.y, o[5]);
        o[6] = fmaf(zv, w1.z, o[6]); o[7] = fmaf(zv, w1.w, o[7]);
    }
    ushort hh[8], hl[8];
    #pragma unroll
    for (int jj = 0; jj < 8; jj++) {
        float v = fmaxf(o[jj], 0.0f);
        __nv_bfloat16 hi = __float2bfloat16_rn(v);
        __nv_bfloat16 lo = __float2bfloat16_rn(v - __bfloat162float(hi));
        hh[jj] = __bfloat16_as_ushort(hi);
        hl[jj] = __bfloat16_as_ushort(lo);
    }
    int ng = blockIdx.x * 8 + n2;
    size_t base = ((size_t)(q * 4 + t2) * NPAD + ng) * 64 + j0;
    *(uint4*)(d_h2h + base) = *(uint4*)hh;
    *(uint4*)(d_h2l + base) = *(uint4*)hl;
}

// ---------------- B precompute (reordered gate columns, bf16 hi/lo) ----------------
__global__ void bprep_kernel(const float* __restrict__ Wih, const float* __restrict__ Whh) {
    int id = blockIdx.x * 256 + threadIdx.x;
    if (id >= 2 * 512 * 24) return;
    int p = id / (512 * 24);
    int rem = id - p * (512 * 24);
    int cg = rem / 24, u = rem % 24;
    int nb = cg >> 7, c = cg & 127;
    int wn = c >> 6, g = (c >> 4) & 3, jh = (c >> 3) & 1, s = c & 7;
    int jg = nb * 32 + wn * 16 + jh * 8 + s;
    int G = g * 128 + jg;
    union { __nv_bfloat16 h[8]; uint4 q; } up;
    #pragma unroll
    for (int e = 0; e < 8; e++) {
        int k = u * 8 + e;
        float v = (k < 64) ? Wih[G * 64 + k] : Whh[G * 128 + (k - 64)];
        __nv_bfloat16 hi = __float2bfloat16_rn(v);
        up.h[e] = p ? __float2bfloat16_rn(v - __bfloat162float(hi)) : hi;
    }
    d_Bp[(size_t)(p * 512 + cg) * 24 + u] = up.q;
}

// ---------------- fused gates GEMM (mma.sync bf16, pre-split inputs) + LSTM ----------------
__global__ void __launch_bounds__(256, 1) gates_mma(
    const float* __restrict__ bih, const float* __restrict__ bhh,
    const __nv_bfloat16* __restrict__ h2h, const __nv_bfloat16* __restrict__ h2l,
    const __nv_bfloat16* __restrict__ hhp, const __nv_bfloat16* __restrict__ hlp,
    __nv_bfloat16* __restrict__ hhn, __nv_bfloat16* __restrict__ hln) {
    extern __shared__ char smem[];
    float* bs = (float*)smem;
    int tid = threadIdx.x, lane = tid & 31, wid = tid >> 5;
    int nb = blockIdx.x;
    int tile0 = blockIdx.y * 128;

    for (int j = tid; j < 512; j += 256) bs[j] = bih[j] + bhh[j];

    // stage B hi+lo (pure copy, weights pre-split)
    for (int i = tid; i < 2 * 128 * 24; i += 256) {
        int p = i / (128 * 24);
        int rem = i - p * (128 * 24);
        int col = rem / 24, u = rem % 24;
        uint4 v = d_Bp[(size_t)(p * 512 + nb * 128 + col) * 24 + u];
        *(uint4*)(smem + B_OFF + p * APLANE + col * (KPAD * 2) + u * 16) = v;
    }
    // stage A hi+lo (pure copy, inputs pre-split)
    for (int i = tid; i < 2 * 128 * 24; i += 256) {
        int p = i / (128 * 24);
        int rem = i - p * (128 * 24);
        int row = rem / 24, u = rem % 24;
        int n = tile0 + row;
        const __nv_bfloat16* src;
        if (u < 8) src = (p ? h2l : h2h) + (size_t)n * 64 + u * 8;
        else       src = (p ? hlp : hhp) + (size_t)n * 128 + (u - 8) * 8;
        *(uint4*)(smem + A_OFF + p * APLANE + row * (KPAD * 2) + u * 16) = *(const uint4*)src;
    }
    __syncthreads();

    int wm = wid & 3;
    int wn = wid >> 2;
    float acc[2][8][4];
    #pragma unroll
    for (int mi = 0; mi < 2; mi++)
        #pragma unroll
        for (int nt = 0; nt < 8; nt++)
            #pragma unroll
            for (int r = 0; r < 4; r++) acc[mi][nt][r] = 0.0f;

    uint32_t sb = smem_u32(smem);
    int q = lane >> 3, r8 = lane & 7;
    uint32_t aRowOff = (uint32_t)((wm * 32 + (q & 1) * 8 + r8) * (KPAD * 2) + ((q >> 1) * 8) * 2);
    uint32_t bRowBase = (uint32_t)((wn * 64 + (q >> 1) * 8 + r8) * (KPAD * 2) + (q & 1) * 16);

    #pragma unroll 1
    for (int pass = 0; pass < 3; pass++) {
        uint32_t aBase = sb + A_OFF + (pass == 2 ? APLANE : 0) + aRowOff;
        uint32_t bBase = sb + B_OFF + (pass == 1 ? APLANE : 0) + bRowBase;
        #pragma unroll 1
        for (int ks = 0; ks < 12; ks++) {
            uint32_t a[2][4];
            #pragma unroll
            for (int mi = 0; mi < 2; mi++)
                ldsm4(a[mi], aBase + mi * (16 * KPAD * 2) + ks * 32);
            uint32_t b[8][2];
            #pragma unroll
            for (int pr = 0; pr < 4; pr++) {
                uint32_t t4[4];
                ldsm4(t4, bBase + pr * (16 * KPAD * 2) + ks * 32);
                b[2 * pr][0] = t4[0]; b[2 * pr][1] = t4[1];
                b[2 * pr + 1][0] = t4[2]; b[2 * pr + 1][1] = t4[3];
            }
            #pragma unroll
            for (int mi = 0; mi < 2; mi++)
                #pragma unroll
                for (int nt = 0; nt < 8; nt++)
                    mma16816(acc[mi][nt], a[mi], b[nt]);
        }
    }

    // ---- fused LSTM epilogue, smem-staged coalesced I/O ----
    __syncthreads();
    float (*c_s)[33] = (float(*)[33])(smem + A_OFF);
    uint  (*h_s)[33] = (uint (*)[33])(smem + A_OFF + 17408);
    // stage c tile in (coalesced float4)
    for (int i = tid; i < 1024; i += 256) {
        int r = i >> 3, q4 = i & 7;
        float4 v = *(const float4*)(d_cs2 + ((size_t)nb * NPAD + tile0 + r) * 32 + q4 * 4);
        c_s[r][q4 * 4 + 0] = v.x; c_s[r][q4 * 4 + 1] = v.y;
        c_s[r][q4 * 4 + 2] = v.z; c_s[r][q4 * 4 + 3] = v.w;
    }
    __syncthreads();
    {
        int gq = lane >> 2, t = lane & 3;
        #pragma unroll
        for (int mi = 0; mi < 2; mi++) {
            #pragma unroll
            for (int h = 0; h < 2; h++) {
                int rl = wm * 32 + mi * 16 + h * 8 + gq;
                #pragma unroll
                for (int jh = 0; jh < 2; jh++) {
                    #pragma unroll
                    for (int p = 0; p < 2; p++) {
                        int jl = wn * 16 + jh * 8 + 2 * t + p;
                        int jg = nb * 32 + jl;
                        int ci = h * 2 + p;
                        float gi = acc[mi][0 + jh][ci] + bs[jg];
                        float gf = acc[mi][2 + jh][ci] + bs[128 + jg];
                        float gG = acc[mi][4 + jh][ci] + bs[256 + jg];
                        float go = acc[mi][6 + jh][ci] + bs[384 + jg];
                        float cp = c_s[rl][jl];
                        float si = 1.0f / (1.0f + __expf(-gi));
                        float sf = 1.0f / (1.0f + __expf(-gf));
                        float so = 1.0f / (1.0f + __expf(-go));
                        float cn = sf * cp + si * tanhf(gG);
                        float hv = so * tanhf(cn);
                        c_s[rl][jl] = cn;
                        __nv_bfloat16 hi = __float2bfloat16_rn(hv);
                        __nv_bfloat16 lo = __float2bfloat16_rn(hv - __bfloat162float(hi));
                        h_s[rl][jl] = ((uint)__bfloat16_as_ushort(lo) << 16) |
                                      (uint)__bfloat16_as_ushort(hi);
                    }
                }
            }
        }
    }
    __syncthreads();
    // write c back (coalesced float4)
    for (int i = tid; i < 1024; i += 256) {
        int r = i >> 3, q4 = i & 7;
        float4 v = make_float4(c_s[r][q4 * 4 + 0], c_s[r][q4 * 4 + 1],
                               c_s[r][q4 * 4 + 2], c_s[r][q4 * 4 + 3]);
        *(float4*)(d_cs2 + ((size_t)nb * NPAD + tile0 + r) * 32 + q4 * 4) = v;
    }
    // write h hi/lo (32-bit stores, 2 cols per thread)
    for (int i = tid; i < 2048; i += 256) {
        int r = i >> 4, c2 = i & 15;
        uint u0 = h_s[r][c2 * 2], u1 = h_s[r][c2 * 2 + 1];
        size_t base = ((size_t)(tile0 + r)) * 128 + nb * 32 + c2 * 2;
        *(uint*)(hhn + base) = (u0 & 0xffffu) | (u1 << 16);
        *(uint*)(hln + base) = (u0 >> 16) | (u1 & 0xffff0000u);
    }
}

// ---------------- FC head ----------------
__global__ void fc_kernel(const __nv_bfloat16* __restrict__ hh,
                          const __nv_bfloat16* __restrict__ hl,
                          const float* __restrict__ Wf1, const float* __restrict__ bf1,
                          const float* __restrict__ Wf2, const float* __restrict__ bf2,
                          float* __restrict__ out) {
    __shared__ float Ws[LH * 32];
    __shared__ float hsm[32][LH];
    int tid = threadIdx.x;
    for (int i = tid; i < LH * 32; i += 256) Ws[i] = Wf1[i];
    int n0 = blockIdx.x * 32;
    for (int i = tid; i < 32 * LH; i += 256) {
        int nl = i >> 7, k = i & 127;
        int n = n0 + nl;
        float v = 0.0f;
        if (n < NN) {
            size_t idx = (size_t)n * 128 + k;
            v = __bfloat162float(hh[idx]) + __bfloat162float(hl[idx]);
        }
        hsm[nl][k] = v;
    }
    __syncthreads();
    int w = tid >> 5, lane = tid & 31;
    float wf2 = Wf2[lane];
    float bb1 = bf1[lane];
    for (int r = 0; r < 4; r++) {
        int nl = w * 4 + r;
        int n = n0 + nl;
        float acc = bb1;
        #pragma unroll
        for (int k = 0; k < LH; k++) acc = fmaf(hsm[nl][k], Ws[k * 32 + lane], acc);
        acc = fmaxf(acc, 0.0f) * wf2;
        #pragma unroll
        for (int off = 16; off > 0; off >>= 1)
            acc += __shfl_down_sync(0xffffffffu, acc, off);
        if (lane == 0 && n < NN) out[n] = acc + bf2[0];
    }
}

// ---------------- launcher ----------------
extern "C" void kernel_launch(void* const* d_in, const int* in_sizes, int n_in,
                              void* d_out, int out_size) {
    const float* x_seq = (const float*)d_in[0];
    const int*   ei    = (const int*)d_in[1];
    const float* W1    = (const float*)d_in[2];
    const float* b1    = (const float*)d_in[3];
    const float* W2    = (const float*)d_in[4];
    const float* b2    = (const float*)d_in[5];
    const float* Wih   = (const float*)d_in[6];
    const float* Whh   = (const float*)d_in[7];
    const float* bih   = (const float*)d_in[8];
    const float* bhh   = (const float*)d_in[9];
    const float* Wf1   = (const float*)d_in[10];
    const float* bf1   = (const float*)d_in[11];
    const float* Wf2   = (const float*)d_in[12];
    const float* bf2   = (const float*)d_in[13];
    float* out = (float*)d_out;

    cudaFuncSetAttribute(gates_mma, cudaFuncAttributeMaxDynamicSharedMemorySize, GATES_SMEM);

    void *degp, *csp, *hh0p, *hl0p;
    cudaGetSymbolAddress(&degp, d_deg);
    cudaGetSymbolAddress(&csp, d_cs2);
    cudaGetSymbolAddress(&hh0p, d_hh0);
    cudaGetSymbolAddress(&hl0p, d_hl0);
    cudaMemsetAsync(degp, 0, NN * sizeof(int));
    cudaMemsetAsync(csp, 0, (size_t)4 * NPAD * 32 * sizeof(float));
    cudaMemsetAsync(hh0p, 0, (size_t)NPAD * 128 * 2);
    cudaMemsetAsync(hl0p, 0, (size_t)NPAD * 128 * 2);

    __nv_bfloat16 *hh0, *hl0, *hh1, *hl1, *h2hB, *h2lB;
    cudaGetSymbolAddress((void**)&hh0, d_hh0);
    cudaGetSymbolAddress((void**)&hl0, d_hl0);
    cudaGetSymbolAddress((void**)&hh1, d_hh1);
    cudaGetSymbolAddress((void**)&hl1, d_hl1);
    cudaGetSymbolAddress((void**)&h2hB, d_h2h);
    cudaGetSymbolAddress((void**)&h2lB, d_h2l);

    deg_kernel<<<(EE + 255) / 256, 256>>>(ei);
    dinv_kernel<<<(NN + 255) / 256, 256>>>();
    scan_block_kernel<<<SCAN_NB, 512>>>();
    scan_top_kernel<<<1, 32>>>();
    scan_add_kernel<<<(NN + 255) / 256, 256>>>();
    csr_fill_kernel<<<(EE + 255) / 256, 256>>>(ei);
    bprep_kernel<<<(2 * 512 * 24 + 255) / 256, 256>>>(Wih, Whh);
    xprep_kernel<<<(NN * 96 + 255) / 256, 256>>>(x_seq);

    agg1mm1_kernel<<<dim3(NN / 8, 3), 256>>>(W1, b1);
    agg2mm2_kernel<<<dim3(NN / 8, 6), 256>>>(W2, b2);

    dim3 ggrid(4, (NN + 127) / 128);
    for (int t = 0; t < T_STEPS; t++) {
        const __nv_bfloat16* hhp = (t & 1) ? hh1 : hh0;
        const __nv_bfloat16* hlp = (t & 1) ? hl1 : hl0;
        __nv_bfloat16* hhn = (t & 1) ? hh0 : hh1;
        __nv_bfloat16* hln = (t & 1) ? hl0 : hl1;
        gates_mma<<<ggrid, 256, GATES_SMEM>>>(
            bih, bhh,
            h2hB + (size_t)t * NPAD * 64, h2lB + (size_t)t * NPAD * 64,
            hhp, hlp, hhn, hln);
    }
    fc_kernel<<<(NN + 31) / 32, 256>>>(hh0, hl0, Wf1, bf1, Wf2, bf2, out);
}

// round 5
// speedup vs baseline: 2.3627x; 1.7035x over previous
#include <cuda_runtime.h>
#include <cuda_bf16.h>
#include <cuda_fp16.h>
#include <math.h>
#include <stdint.h>

#define T_STEPS 24
#define NN 50000
#define NPAD 50048
#define EE 1600000
#define F 16
#define H 64
#define LH 128
#define SCAN_NB 98

#define NTILES64 782            // NPAD/64
#define NCTAS 148
#define NGRP 37                 // CTAs per nb group

// persistent-kernel smem layout
#define BIAS_OFF 0              // 512 floats = 2048 B
#define BOFF 2048               // B hi+lo: 2 * 128 * 400 = 102400
#define AOFF (2048 + 102400)    // A double buffer: 2 * 51200
#define PERSIST_SMEM (AOFF + 2 * 51200)   // 206848

// ---------------- helpers ----------------
__device__ __forceinline__ uint32_t smem_u32(const void* p) {
    uint32_t a;
    asm("{ .reg .u64 t; cvta.to.shared.u64 t, %1; cvt.u32.u64 %0, t; }" : "=r"(a) : "l"(p));
    return a;
}
__device__ __forceinline__ void ldsm4(uint32_t* r, uint32_t addr) {
    asm volatile("ldmatrix.sync.aligned.m8n8.x4.shared.b16 {%0,%1,%2,%3}, [%4];"
                 : "=r"(r[0]), "=r"(r[1]), "=r"(r[2]), "=r"(r[3]) : "r"(addr));
}
__device__ __forceinline__ void mma16816(float* c, const uint32_t* a, const uint32_t* b) {
    asm volatile(
        "mma.sync.aligned.m16n8k16.row.col.f32.bf16.bf16.f32 "
        "{%0,%1,%2,%3}, {%4,%5,%6,%7}, {%8,%9}, {%0,%1,%2,%3};"
        : "+f"(c[0]), "+f"(c[1]), "+f"(c[2]), "+f"(c[3])
        : "r"(a[0]), "r"(a[1]), "r"(a[2]), "r"(a[3]), "r"(b[0]), "r"(b[1]));
}
__device__ __forceinline__ void cp16(uint32_t dst, const void* src) {
    asm volatile("cp.async.cg.shared.global [%0], [%1], 16;" :: "r"(dst), "l"(src));
}
__device__ __forceinline__ float sigf(float x) {
    return __fdividef(1.0f, 1.0f + __expf(-x));
}
__device__ __forceinline__ float tanhfast(float x) {
    float e = __expf(-2.0f * fabsf(x));
    float r = __fdividef(1.0f - e, 1.0f + e);
    return copysignf(r, x);
}

// ---------------- scratch ----------------
__device__ int   d_deg[NN];
__device__ int   d_rowptr[NN + 1];
__device__ int   d_cursor[NN];
__device__ int   d_csr[EE];
__device__ int   d_blocksum[128];
__device__ int   d_blockoff[128];
__device__ float d_dinv[NN];
__device__ unsigned d_bar;
__device__ __half d_xh[19200000];                 // [n][t*16+c]
__device__ __half d_h1[76800000];                 // [t][n][64]
__device__ __nv_bfloat16 d_h2h[76873728];         // [t][NPAD][64] hi
__device__ __nv_bfloat16 d_h2l[76873728];         // lo
__device__ __nv_bfloat16 d_hh0[6406144];          // [NPAD][128]
__device__ __nv_bfloat16 d_hl0[6406144];
__device__ __nv_bfloat16 d_hh1[6406144];
__device__ __nv_bfloat16 d_hl1[6406144];
__device__ float d_cs2[6406144];                  // [nb][NPAD][32]
__device__ uint4 d_Bp[2 * 512 * 24];              // bf16 hi/lo weights, reordered cols

// ---------------- CSR build ----------------
__global__ void deg_kernel(const int* __restrict__ ei) {
    int e = blockIdx.x * 256 + threadIdx.x;
    if (e < EE) atomicAdd(&d_deg[ei[EE + e]], 1);
}
__global__ void dinv_kernel() {
    int n = blockIdx.x * 256 + threadIdx.x;
    if (n == 0) d_bar = 0;
    if (n < NN) d_dinv[n] = rsqrtf((float)d_deg[n] + 1.0f);
}
__global__ void scan_block_kernel() {
    __shared__ int s[512];
    int tid = threadIdx.x;
    int i = blockIdx.x * 512 + tid;
    int v = (i < NN) ? d_deg[i] : 0;
    s[tid] = v;
    __syncthreads();
    #pragma unroll
    for (int off = 1; off < 512; off <<= 1) {
        int t = (tid >= off) ? s[tid - off] : 0;
        __syncthreads();
        s[tid] += t;
        __syncthreads();
    }
    if (i < NN) d_rowptr[i + 1] = s[tid];
    if (tid == 511) d_blocksum[blockIdx.x] = s[511];
}
__global__ void scan_top_kernel() {
    if (threadIdx.x == 0) {
        int run = 0;
        for (int b = 0; b < SCAN_NB; b++) { d_blockoff[b] = run; run += d_blocksum[b]; }
    }
}
__global__ void scan_add_kernel() {
    int i = blockIdx.x * 256 + threadIdx.x;
    if (i == 0) { d_rowptr[0] = 0; d_cursor[0] = 0; }
    if (i < NN) {
        int v = d_rowptr[i + 1] + d_blockoff[i >> 9];
        d_rowptr[i + 1] = v;
        if (i + 1 < NN) d_cursor[i + 1] = v;
    }
}
__global__ void csr_fill_kernel(const int* __restrict__ ei) {
    int e = blockIdx.x * 256 + threadIdx.x;
    if (e < EE) {
        int s = ei[e];
        int d = ei[EE + e];
        int idx = atomicAdd(&d_cursor[d], 1);
        d_csr[idx] = s;
    }
}

// ---------------- x -> fp16 repack ----------------
__global__ void xprep_kernel(const float* __restrict__ x_seq) {
    int id = blockIdx.x * 256 + threadIdx.x;
    if (id >= NN * 96) return;
    int n = id / 96, r = id % 96;
    int t = r >> 2, c4 = r & 3;
    float4 v = *(const float4*)(x_seq + ((size_t)t * NN + n) * F + c4 * 4);
    __half h[4] = {__float2half_rn(v.x), __float2half_rn(v.y),
                   __float2half_rn(v.z), __float2half_rn(v.w)};
    *(uint2*)(d_xh + (size_t)n * 384 + r * 4) = *(uint2*)h;
}

// ---------------- fused agg1 + mm1 (8-t chunks) ----------------
__global__ void __launch_bounds__(256) agg1mm1_kernel(const float* __restrict__ W1,
                                                      const float* __restrict__ b1) {
    __shared__ float W1s[F * H];
    __shared__ float b1s[H];
    __shared__ float ys[8][128];
    int tid = threadIdx.x, w = tid >> 5, lane = tid & 31;
    for (int i = tid; i < F * H; i += 256) W1s[i] = W1[i];
    if (tid < H) b1s[tid] = b1[tid];
    int n = blockIdx.x * 8 + w;
    int q = blockIdx.y;
    float dn = d_dinv[n];
    const uint2* xr = (const uint2*)d_xh;
    uint2 u = xr[(size_t)n * 96 + q * 32 + lane];
    float2 p0 = __half22float2(*(__half2*)&u.x);
    float2 p1 = __half22float2(*(__half2*)&u.y);
    float sn = dn * dn;
    float a0 = p0.x * sn, a1 = p0.y * sn, a2 = p1.x * sn, a3 = p1.y * sn;
    int e0 = d_rowptr[n], e1 = d_rowptr[n + 1];
    #pragma unroll 4
    for (int e = e0; e < e1; e++) {
        int s = d_csr[e];
        float wgt = d_dinv[s] * dn;
        uint2 v = xr[(size_t)s * 96 + q * 32 + lane];
        float2 q0 = __half22float2(*(__half2*)&v.x);
        float2 q1 = __half22float2(*(__half2*)&v.y);
        a0 = fmaf(q0.x, wgt, a0); a1 = fmaf(q0.y, wgt, a1);
        a2 = fmaf(q1.x, wgt, a2); a3 = fmaf(q1.y, wgt, a3);
    }
    ys[w][lane * 4 + 0] = a0; ys[w][lane * 4 + 1] = a1;
    ys[w][lane * 4 + 2] = a2; ys[w][lane * 4 + 3] = a3;
    __syncthreads();
    int n2 = tid >> 5, t2 = lane >> 2, jq = lane & 3;
    float yv[16];
    #pragma unroll
    for (int k = 0; k < 16; k++) yv[k] = ys[n2][t2 * 16 + k];
    float o[16];
    #pragma unroll
    for (int jj = 0; jj < 16; jj++) o[jj] = b1s[jq * 16 + jj];
    #pragma unroll
    for (int k = 0; k < 16; k++)
        #pragma unroll
        for (int jj = 0; jj < 16; jj++)
            o[jj] = fmaf(yv[k], W1s[k * 64 + jq * 16 + jj], o[jj]);
    __half hp[16];
    #pragma unroll
    for (int jj = 0; jj < 16; jj++) hp[jj] = __float2half_rn(fmaxf(o[jj], 0.0f));
    int tg = q * 8 + t2;
    int ng = blockIdx.x * 8 + n2;
    __half* dst = d_h1 + ((size_t)tg * NN + ng) * 64 + jq * 16;
    *(uint4*)dst = *(uint4*)hp;
    *(uint4*)(dst + 8) = *(uint4*)(hp + 8);
}

// ---------------- fused agg2 + mm2 (4-t chunks) ----------------
__global__ void __launch_bounds__(256) agg2mm2_kernel(const float* __restrict__ W2,
                                                      const float* __restrict__ b2) {
    __shared__ float W2s[H * H];
    __shared__ float b2s[H];
    __shared__ float zs[8][4][64];
    int tid = threadIdx.x, w = tid >> 5, lane = tid & 31;
    for (int i = tid; i < H * H; i += 256) W2s[i] = W2[i];
    if (tid < H) b2s[tid] = b2[tid];
    int n = blockIdx.x * 8 + w;
    int q = blockIdx.y;
    float dn = d_dinv[n];
    const uint* h1u = (const uint*)d_h1;
    float acc[4][2];
    float sn = dn * dn;
    #pragma unroll
    for (int tt = 0; tt < 4; tt++) {
        uint u = h1u[((size_t)(q * 4 + tt) * NN + n) * 32 + lane];
        float2 p = __half22float2(*(__half2*)&u);
        acc[tt][0] = p.x * sn; acc[tt][1] = p.y * sn;
    }
    int e0 = d_rowptr[n], e1 = d_rowptr[n + 1];
    #pragma unroll 2
    for (int e = e0; e < e1; e++) {
        int s = d_csr[e];
        float wgt = d_dinv[s] * dn;
        #pragma unroll
        for (int tt = 0; tt < 4; tt++) {
            uint u = h1u[((size_t)(q * 4 + tt) * NN + s) * 32 + lane];
            float2 p = __half22float2(*(__half2*)&u);
            acc[tt][0] = fmaf(p.x, wgt, acc[tt][0]);
            acc[tt][1] = fmaf(p.y, wgt, acc[tt][1]);
        }
    }
    #pragma unroll
    for (int tt = 0; tt < 4; tt++) {
        zs[w][tt][lane * 2] = acc[tt][0];
        zs[w][tt][lane * 2 + 1] = acc[tt][1];
    }
    __syncthreads();
    int n2 = tid >> 5, t2 = (lane >> 3) & 3, j0 = (lane & 7) * 8;
    float o[8];
    #pragma unroll
    for (int jj = 0; jj < 8; jj++) o[jj] = b2s[j0 + jj];
    #pragma unroll 8
    for (int k = 0; k < 64; k++) {
        float zv = zs[n2][t2][k];
        float4 w0 = *(float4*)(W2s + k * 64 + j0);
        float4 w1 = *(float4*)(W2s + k * 64 + j0 + 4);
        o[0] = fmaf(zv, w0.x, o[0]); o[1] = fmaf(zv, w0.y, o[1]);
        o[2] = fmaf(zv, w0.z, o[2]); o[3] = fmaf(zv, w0.w, o[3]);
        o[4] = fmaf(zv, w1.x, o[4]); o[5] = fmaf(zv, w1.y, o[5]);
        o[6] = fmaf(zv, w1.z, o[6]); o[7] = fmaf(zv, w1.w, o[7]);
    }
    ushort hh[8], hl[8];
    #pragma unroll
    for (int jj = 0; jj < 8; jj++) {
        float v = fmaxf(o[jj], 0.0f);
        __nv_bfloat16 hi = __float2bfloat16_rn(v);
        __nv_bfloat16 lo = __float2bfloat16_rn(v - __bfloat162float(hi));
        hh[jj] = __bfloat16_as_ushort(hi);
        hl[jj] = __bfloat16_as_ushort(lo);
    }
    int ng = blockIdx.x * 8 + n2;
    size_t base = ((size_t)(q * 4 + t2) * NPAD + ng) * 64 + j0;
    *(uint4*)(d_h2h + base) = *(uint4*)hh;
    *(uint4*)(d_h2l + base) = *(uint4*)hl;
}

// ---------------- B precompute (bf16 hi/lo, reordered: nt = gate) ----------------
// local col c in [0,128): wn=c>>5, g=(c>>3)&3, s=c&7 ; jg = nb*32 + wn*8 + s ; G = g*128 + jg
__global__ void bprep_kernel(const float* __restrict__ Wih, const float* __restrict__ Whh) {
    int id = blockIdx.x * 256 + threadIdx.x;
    if (id >= 2 * 512 * 24) return;
    int p = id / (512 * 24);
    int rem = id - p * (512 * 24);
    int cg = rem / 24, u = rem % 24;
    int nb = cg >> 7, c = cg & 127;
    int wn = c >> 5, g = (c >> 3) & 3, s = c & 7;
    int jg = nb * 32 + wn * 8 + s;
    int G = g * 128 + jg;
    union { __nv_bfloat16 h[8]; uint4 q; } up;
    #pragma unroll
    for (int e = 0; e < 8; e++) {
        int k = u * 8 + e;
        float v = (k < 64) ? Wih[G * 64 + k] : Whh[G * 128 + (k - 64)];
        __nv_bfloat16 hi = __float2bfloat16_rn(v);
        up.h[e] = p ? __float2bfloat16_rn(v - __bfloat162float(hi)) : hi;
    }
    d_Bp[(size_t)(p * 512 + cg) * 24 + u] = up.q;
}

// ---------------- A staging: cp.async into smem buf ----------------
__device__ __forceinline__ void stageA(
    char* smem, uint32_t sb, int buf, int tile, bool zero_h,
    const __nv_bfloat16* h2h, const __nv_bfloat16* h2l,
    const __nv_bfloat16* hhp, const __nv_bfloat16* hlp, int tid) {
    int row0 = tile * 64;
    uint32_t bufb = sb + AOFF + buf * 51200;
    #pragma unroll
    for (int it = 0; it < 12; it++) {
        int i = tid + it * 256;                  // 0..3071
        int p = i >> 10;                         // /1536? no: 2*64*24=3072; plane = i/1536
        p = i / 1536;
        int rem = i - p * 1536;
        int row = rem / 24, u = rem % 24;
        uint32_t dst = bufb + p * 25600 + row * 400 + u * 16;
        if (u < 8) {
            cp16(dst, (p ? h2l : h2h) + (size_t)(row0 + row) * 64 + u * 8);
        } else if (!zero_h) {
            cp16(dst, (p ? hlp : hhp) + (size_t)(row0 + row) * 128 + (u - 8) * 8);
        } else {
            *(uint4*)(smem + AOFF + buf * 51200 + p * 25600 + row * 400 + u * 16) =
                make_uint4(0, 0, 0, 0);
        }
    }
    asm volatile("cp.async.commit_group;" ::: "memory");
}

// ---------------- persistent LSTM: all 24 steps, one kernel ----------------
__global__ void __launch_bounds__(256, 1) lstm_persist(const float* __restrict__ bih,
                                                       const float* __restrict__ bhh) {
    extern __shared__ char smem[];
    float* bs = (float*)smem;
    uint32_t sb = smem_u32(smem);
    const int tid = threadIdx.x, lane = tid & 31, wid = tid >> 5;
    const int nb = blockIdx.x & 3;
    const int gidx = blockIdx.x >> 2;          // 0..36
    const int cnt = (gidx < NTILES64 - NGRP * 21) ? 22 : 21;   // 782 = 37*21+5

    // one-time: bias + B (hi/lo) into smem
    for (int j = tid; j < 512; j += 256) bs[j] = bih[j] + bhh[j];
    for (int i = tid; i < 2 * 128 * 24; i += 256) {
        int p = i / (128 * 24);
        int rem = i - p * (128 * 24);
        int col = rem / 24, u = rem % 24;
        uint4 v = d_Bp[(size_t)(p * 512 + nb * 128 + col) * 24 + u];
        *(uint4*)(smem + BOFF + p * 51200 + col * 400 + u * 16) = v;
    }
    __syncthreads();

    const int wm = wid & 1;                    // 2 row groups of 32
    const int wn = wid >> 1;                   // 4 col groups of 32
    const int q = lane >> 3, r8 = lane & 7;
    const uint32_t aRowOff = (uint32_t)((wm * 32 + (q & 1) * 8 + r8) * 400 + ((q >> 1) * 8) * 2);
    const uint32_t bRowBase = (uint32_t)((wn * 32 + (q >> 1) * 8 + r8) * 400 + (q & 1) * 16);
    const int gq = lane >> 2, tq = lane & 3;

    for (int t = 0; t < T_STEPS; t++) {
        const __nv_bfloat16* h2h = d_h2h + (size_t)t * NPAD * 64;
        const __nv_bfloat16* h2l = d_h2l + (size_t)t * NPAD * 64;
        const __nv_bfloat16* hhp = (t & 1) ? d_hh1 : d_hh0;
        const __nv_bfloat16* hlp = (t & 1) ? d_hl1 : d_hl0;
        __nv_bfloat16* hhn = (t & 1) ? d_hh0 : d_hh1;
        __nv_bfloat16* hln = (t & 1) ? d_hl0 : d_hl1;
        const bool z = (t == 0);

        stageA(smem, sb, 0, gidx, z, h2h, h2l, hhp, hlp, tid);

        for (int k = 0; k < cnt; k++) {
            int tile = gidx + k * NGRP;
            if (k + 1 < cnt) {
                stageA(smem, sb, (k + 1) & 1, gidx + (k + 1) * NGRP, z, h2h, h2l, hhp, hlp, tid);
                asm volatile("cp.async.wait_group 1;" ::: "memory");
            } else {
                asm volatile("cp.async.wait_group 0;" ::: "memory");
            }
            __syncthreads();

            float acc[2][4][4];
            #pragma unroll
            for (int mi = 0; mi < 2; mi++)
                #pragma unroll
                for (int nt = 0; nt < 4; nt++)
                    #pragma unroll
                    for (int r = 0; r < 4; r++) acc[mi][nt][r] = 0.0f;

            uint32_t abufb = sb + AOFF + (k & 1) * 51200;
            #pragma unroll 1
            for (int pass = 0; pass < 3; pass++) {
                uint32_t aB = abufb + (pass == 2 ? 25600 : 0) + aRowOff;
                uint32_t bB = sb + BOFF + (pass == 1 ? 51200 : 0) + bRowBase;
                #pragma unroll 1
                for (int ks = 0; ks < 12; ks++) {
                    uint32_t a[2][4];
                    ldsm4(a[0], aB + ks * 32);
                    ldsm4(a[1], aB + 16 * 400 + ks * 32);
                    uint32_t b[4][2];
                    {
                        uint32_t t4[4];
                        ldsm4(t4, bB + ks * 32);
                        b[0][0] = t4[0]; b[0][1] = t4[1];
                        b[1][0] = t4[2]; b[1][1] = t4[3];
                    }
                    {
                        uint32_t t4[4];
                        ldsm4(t4, bB + 16 * 400 + ks * 32);
                        b[2][0] = t4[0]; b[2][1] = t4[1];
                        b[3][0] = t4[2]; b[3][1] = t4[3];
                    }
                    #pragma unroll
                    for (int mi = 0; mi < 2; mi++)
                        #pragma unroll
                        for (int nt = 0; nt < 4; nt++)
                            mma16816(acc[mi][nt], a[mi], b[nt]);
                }
            }

            // fused LSTM epilogue (register-resident gates)
            int row0 = tile * 64;
            #pragma unroll
            for (int mi = 0; mi < 2; mi++) {
                #pragma unroll
                for (int h = 0; h < 2; h++) {
                    int rl = wm * 32 + mi * 16 + h * 8 + gq;
                    int n = row0 + rl;
                    float* cptr = d_cs2 + ((size_t)nb * NPAD + n) * 32 + wn * 8 + tq * 2;
                    float2 cp = z ? make_float2(0.0f, 0.0f) : *(float2*)cptr;
                    uint hiPack = 0, loPack = 0;
                    #pragma unroll
                    for (int p = 0; p < 2; p++) {
                        int jgl = nb * 32 + wn * 8 + tq * 2 + p;
                        int ci = h * 2 + p;
                        float gi = acc[mi][0][ci] + bs[jgl];
                        float gf = acc[mi][1][ci] + bs[128 + jgl];
                        float gG = acc[mi][2][ci] + bs[256 + jgl];
                        float go = acc[mi][3][ci] + bs[384 + jgl];
                        float cold = p ? cp.y : cp.x;
                        float cn = sigf(gf) * cold + sigf(gi) * tanhfast(gG);
                        float hv = sigf(go) * tanhfast(cn);
                        if (p) cp.y = cn; else cp.x = cn;
                        __nv_bfloat16 hi = __float2bfloat16_rn(hv);
                        __nv_bfloat16 lo = __float2bfloat16_rn(hv - __bfloat162float(hi));
                        hiPack |= ((uint)__bfloat16_as_ushort(hi)) << (16 * p);
                        loPack |= ((uint)__bfloat16_as_ushort(lo)) << (16 * p);
                    }
                    *(float2*)cptr = cp;
                    size_t hb = (size_t)n * 128 + nb * 32 + wn * 8 + tq * 2;
                    *(uint*)(hhn + hb) = hiPack;
                    *(uint*)(hln + hb) = loPack;
                }
            }
            __syncthreads();
        }

        // grid-wide barrier between steps
        if (t < T_STEPS - 1) {
            __syncthreads();
            if (tid == 0) {
                __threadfence();
                atomicAdd(&d_bar, 1u);
                unsigned target = (unsigned)NCTAS * (unsigned)(t + 1);
                unsigned v;
                do {
                    asm volatile("ld.acquire.gpu.global.u32 %0, [%1];"
                                 : "=r"(v) : "l"(&d_bar) : "memory");
                    if (v < target) asm volatile("nanosleep.u32 64;");
                } while (v < target);
            }
            __syncthreads();
        }
    }
}

// ---------------- FC head ----------------
__global__ void fc_kernel(const __nv_bfloat16* __restrict__ hh,
                          const __nv_bfloat16* __restrict__ hl,
                          const float* __restrict__ Wf1, const float* __restrict__ bf1,
                          const float* __restrict__ Wf2, const float* __restrict__ bf2,
                          float* __restrict__ out) {
    __shared__ float Ws[LH * 32];
    __shared__ float hsm[32][LH];
    int tid = threadIdx.x;
    for (int i = tid; i < LH * 32; i += 256) Ws[i] = Wf1[i];
    int n0 = blockIdx.x * 32;
    for (int i = tid; i < 32 * LH; i += 256) {
        int nl = i >> 7, k = i & 127;
        int n = n0 + nl;
        float v = 0.0f;
        if (n < NN) {
            size_t idx = (size_t)n * 128 + k;
            v = __bfloat162float(hh[idx]) + __bfloat162float(hl[idx]);
        }
        hsm[nl][k] = v;
    }
    __syncthreads();
    int w = tid >> 5, lane = tid & 31;
    float wf2 = Wf2[lane];
    float bb1 = bf1[lane];
    for (int r = 0; r < 4; r++) {
        int nl = w * 4 + r;
        int n = n0 + nl;
        float acc = bb1;
        #pragma unroll
        for (int k = 0; k < LH; k++) acc = fmaf(hsm[nl][k], Ws[k * 32 + lane], acc);
        acc = fmaxf(acc, 0.0f) * wf2;
        #pragma unroll
        for (int off = 16; off > 0; off >>= 1)
            acc += __shfl_down_sync(0xffffffffu, acc, off);
        if (lane == 0 && n < NN) out[n] = acc + bf2[0];
    }
}

// ---------------- launcher ----------------
extern "C" void kernel_launch(void* const* d_in, const int* in_sizes, int n_in,
                              void* d_out, int out_size) {
    const float* x_seq = (const float*)d_in[0];
    const int*   ei    = (const int*)d_in[1];
    const float* W1    = (const float*)d_in[2];
    const float* b1    = (const float*)d_in[3];
    const float* W2    = (const float*)d_in[4];
    const float* b2    = (const float*)d_in[5];
    const float* Wih   = (const float*)d_in[6];
    const float* Whh   = (const float*)d_in[7];
    const float* bih   = (const float*)d_in[8];
    const float* bhh   = (const float*)d_in[9];
    const float* Wf1   = (const float*)d_in[10];
    const float* bf1   = (const float*)d_in[11];
    const float* Wf2   = (const float*)d_in[12];
    const float* bf2   = (const float*)d_in[13];
    float* out = (float*)d_out;

    cudaFuncSetAttribute(lstm_persist, cudaFuncAttributeMaxDynamicSharedMemorySize,
                         PERSIST_SMEM);

    void* degp;
    cudaGetSymbolAddress(&degp, d_deg);
    cudaMemsetAsync(degp, 0, NN * sizeof(int));

    __nv_bfloat16 *hh0, *hl0;
    cudaGetSymbolAddress((void**)&hh0, d_hh0);
    cudaGetSymbolAddress((void**)&hl0, d_hl0);

    deg_kernel<<<(EE + 255) / 256, 256>>>(ei);
    dinv_kernel<<<(NN + 255) / 256, 256>>>();
    scan_block_kernel<<<SCAN_NB, 512>>>();
    scan_top_kernel<<<1, 32>>>();
    scan_add_kernel<<<(NN + 255) / 256, 256>>>();
    csr_fill_kernel<<<(EE + 255) / 256, 256>>>(ei);
    bprep_kernel<<<(2 * 512 * 24 + 255) / 256, 256>>>(Wih, Whh);
    xprep_kernel<<<(NN * 96 + 255) / 256, 256>>>(x_seq);

    agg1mm1_kernel<<<dim3(NN / 8, 3), 256>>>(W1, b1);
    agg2mm2_kernel<<<dim3(NN / 8, 6), 256>>>(W2, b2);

    lstm_persist<<<NCTAS, 256, PERSIST_SMEM>>>(bih, bhh);

    fc_kernel<<<(NN + 31) / 32, 256>>>(hh0, hl0, Wf1, bf1, Wf2, bf2, out);
}